// round 15
// baseline (speedup 1.0000x reference)
#include <cuda_runtime.h>
#include <cstdint>
#include <math.h>

#define B_ 2
#define T_ 2048
#define C_ 1024
#define H_ 16
#define D_ 64
#define M_ (B_ * T_)          // 4096 rows
#define SCALE_ 0.125f          // 1/sqrt(64)

// Scratch (allocation-free rule: device globals)
static __device__ float g_Q[(size_t)M_ * C_];
static __device__ float g_K[(size_t)M_ * C_];
static __device__ float g_V[(size_t)M_ * C_];
static __device__ float g_A[(size_t)M_ * C_];
// tf32-rounded operand copies
static __device__ float g_X[(size_t)M_ * C_];
static __device__ float g_Wq[(size_t)C_ * C_];
static __device__ float g_Wk[(size_t)C_ * C_];
static __device__ float g_Wv[(size_t)C_ * C_];
static __device__ float g_Wo[(size_t)C_ * C_];

// ===========================================================================
// helpers
// ===========================================================================
__device__ __forceinline__ uint32_t smem_u32(const void* p) {
    uint32_t a;
    asm("{ .reg .u64 t; cvta.to.shared.u64 t, %1; cvt.u32.u64 %0, t; }"
        : "=r"(a) : "l"(p));
    return a;
}
__device__ __forceinline__ float tf32r(float x) {
    uint32_t u;
    asm("cvt.rna.tf32.f32 %0, %1;" : "=r"(u) : "f"(x));
    return __uint_as_float(u);
}
__device__ __forceinline__ void cpa16(uint32_t dst, const float* src) {
    asm volatile("cp.async.ca.shared.global [%0], [%1], 16;" :: "r"(dst), "l"(src));
}
#define CP_COMMIT() asm volatile("cp.async.commit_group;" ::: "memory")
#define CP_WAIT(n)  asm volatile("cp.async.wait_group %0;" :: "n"(n) : "memory")

__device__ __forceinline__ void mma8(float* c, const uint32_t* a, const uint32_t* b) {
    asm volatile(
        "mma.sync.aligned.m16n8k8.row.col.f32.tf32.tf32.f32 "
        "{%0,%1,%2,%3}, {%4,%5,%6,%7}, {%8,%9}, {%0,%1,%2,%3};"
        : "+f"(c[0]), "+f"(c[1]), "+f"(c[2]), "+f"(c[3])
        : "r"(a[0]), "r"(a[1]), "r"(a[2]), "r"(a[3]), "r"(b[0]), "r"(b[1]));
}

// ===========================================================================
// Pre-pass: tf32 rounding (exact tf32 operands for cp.async path)
// ===========================================================================
__global__ __launch_bounds__(256) void cvt_tf32_kernel(const float* __restrict__ in,
                                                       float* __restrict__ out) {
    size_t i = ((size_t)blockIdx.x * 256 + threadIdx.x) * 4;
    float4 v = *(const float4*)(in + i);
    v.x = tf32r(v.x); v.y = tf32r(v.y); v.z = tf32r(v.z); v.w = tf32r(v.w);
    *(float4*)(out + i) = v;
}

// All four weight matrices in one launch (gridDim.z selects the pair).
__global__ __launch_bounds__(256) void cvt_tf32_w4(const float* __restrict__ w0,
                                                   const float* __restrict__ w1,
                                                   const float* __restrict__ w2,
                                                   const float* __restrict__ w3) {
    const float* in = (blockIdx.z == 0) ? w0 : (blockIdx.z == 1) ? w1
                    : (blockIdx.z == 2) ? w2 : w3;
    float* out = (blockIdx.z == 0) ? g_Wq : (blockIdx.z == 1) ? g_Wk
               : (blockIdx.z == 2) ? g_Wv : g_Wo;
    size_t i = ((size_t)blockIdx.x * 256 + threadIdx.x) * 4;
    float4 v = *(const float4*)(in + i);
    v.x = tf32r(v.x); v.y = tf32r(v.y); v.z = tf32r(v.z); v.w = tf32r(v.w);
    *(float4*)(out + i) = v;
}

// ===========================================================================
// tf32 mma.sync GEMM:  C[M,N] = A[M,K] @ W[N,K]^T, A/W pre-rounded to tf32.
// CTA 128x128, 8 warps (warp tile 64x32), k-chunk 16, 3-stage cp.async.
// smem rows padded to 20 floats -> conflict-free fragment loads.
// ROUND: tf32-round outputs (Q/K/V feed attention's raw cp.async loads).
// ===========================================================================
#define KC 16
#define STAGES 3
#define TSTR 20                       // floats per smem row
#define TILE_F (128 * TSTR)           // floats per tile per stage
#define SMEM_MMA (STAGES * 2 * TILE_F * 4)   // 61440 bytes
#define NCHUNK (C_ / KC)              // 64

__device__ __forceinline__ void load_chunk(const float* __restrict__ Ab,
                                           const float* __restrict__ Wb,
                                           float* sA, float* sB,
                                           int c, int tid) {
    const int k0 = c * KC;
#pragma unroll
    for (int it = 0; it < 2; it++) {
        int idx = tid + it * 256;        // 0..511
        int row = idx >> 2;              // 0..127
        int f4  = (idx & 3) << 2;        // 0,4,8,12
        cpa16(smem_u32(sA + row * TSTR + f4), Ab + (size_t)row * C_ + k0 + f4);
        cpa16(smem_u32(sB + row * TSTR + f4), Wb + (size_t)row * C_ + k0 + f4);
    }
}

template <bool ROUND>
__device__ __forceinline__ void gemm_mma_body(const float* __restrict__ A,
                                              const float* __restrict__ W,
                                              float* __restrict__ Cout,
                                              int bm, int bn) {
    extern __shared__ float smem[];
    float* sA = smem;                       // [STAGES][TILE_F]
    float* sB = smem + STAGES * TILE_F;     // [STAGES][TILE_F]

    const int tid = threadIdx.x;
    const int warp = tid >> 5;
    const int lane = tid & 31;
    const int wm = (warp & 1) * 64;
    const int wn = (warp >> 1) * 32;
    const int lg = lane >> 2;      // group id 0..7
    const int lt = lane & 3;       // thread-in-group

    const float* Ab = A + (size_t)bm * C_;
    const float* Wb = W + (size_t)bn * C_;

    float acc[4][4][4];
#pragma unroll
    for (int i = 0; i < 4; i++)
#pragma unroll
        for (int j = 0; j < 4; j++)
#pragma unroll
            for (int r = 0; r < 4; r++) acc[i][j][r] = 0.0f;

    // prologue: stages 0..STAGES-2
#pragma unroll
    for (int c = 0; c < STAGES - 1; c++) {
        load_chunk(Ab, Wb, sA + c * TILE_F, sB + c * TILE_F, c, tid);
        CP_COMMIT();
    }

    for (int c = 0; c < NCHUNK; c++) {
        CP_WAIT(STAGES - 2);
        __syncthreads();
        const int nc = c + STAGES - 1;
        if (nc < NCHUNK)
            load_chunk(Ab, Wb, sA + (nc % STAGES) * TILE_F,
                       sB + (nc % STAGES) * TILE_F, nc, tid);
        CP_COMMIT();

        const uint32_t* cA = (const uint32_t*)(sA + (c % STAGES) * TILE_F);
        const uint32_t* cB = (const uint32_t*)(sB + (c % STAGES) * TILE_F);
#pragma unroll
        for (int kk = 0; kk < 2; kk++) {
            const int k8 = kk * 8;
            uint32_t af[4][4];
#pragma unroll
            for (int mt = 0; mt < 4; mt++) {
                int r0 = wm + mt * 16 + lg;
                af[mt][0] = cA[(r0)     * TSTR + k8 + lt];
                af[mt][1] = cA[(r0 + 8) * TSTR + k8 + lt];
                af[mt][2] = cA[(r0)     * TSTR + k8 + 4 + lt];
                af[mt][3] = cA[(r0 + 8) * TSTR + k8 + 4 + lt];
            }
            uint32_t bf[4][2];
#pragma unroll
            for (int nt = 0; nt < 4; nt++) {
                int n0 = wn + nt * 8 + lg;
                bf[nt][0] = cB[n0 * TSTR + k8 + lt];
                bf[nt][1] = cB[n0 * TSTR + k8 + 4 + lt];
            }
#pragma unroll
            for (int mt = 0; mt < 4; mt++)
#pragma unroll
                for (int nt = 0; nt < 4; nt++)
                    mma8(acc[mt][nt], af[mt], bf[nt]);
        }
    }

    // epilogue: c0,c1 -> (row, 2lt), (row, 2lt+1); c2,c3 -> row+8
#pragma unroll
    for (int mt = 0; mt < 4; mt++) {
#pragma unroll
        for (int nt = 0; nt < 4; nt++) {
            int row = bm + wm + mt * 16 + lg;
            int col = bn + wn + nt * 8 + lt * 2;
            float v0 = acc[mt][nt][0], v1 = acc[mt][nt][1];
            float v2 = acc[mt][nt][2], v3 = acc[mt][nt][3];
            if (ROUND) { v0 = tf32r(v0); v1 = tf32r(v1); v2 = tf32r(v2); v3 = tf32r(v3); }
            *(float2*)(Cout + (size_t)row * C_ + col) = make_float2(v0, v1);
            *(float2*)(Cout + (size_t)(row + 8) * C_ + col) = make_float2(v2, v3);
        }
    }
}

__global__ __launch_bounds__(256) void gemm_mma_qkv() {
    const float* W = (blockIdx.z == 0) ? g_Wq : (blockIdx.z == 1) ? g_Wk : g_Wv;
    float* Cout = (blockIdx.z == 0) ? g_Q : (blockIdx.z == 1) ? g_K : g_V;
    gemm_mma_body<true>(g_X, W, Cout, blockIdx.y * 128, blockIdx.x * 128);
}
__global__ __launch_bounds__(256) void gemm_mma_wo(float* __restrict__ Cout) {
    gemm_mma_body<false>(g_A, g_Wo, Cout, blockIdx.y * 128, blockIdx.x * 128);
}

// ===========================================================================
// Flash-attention with mma.sync tf32 + cp.async double-buffered K/V.
// Q/K/V are pre-rounded to tf32 by the QKV GEMM epilogue -> raw async loads.
// Block = 64 queries x head x batch, 4 warps; warp owns 16 q-rows.
// Smem: Q[64][68], KP[2][64][68] (K tile; P overwrites after S), V[2][64][72].
// Per tile t (buf s): wait group -> sync -> prefetch t+1 into s^1 (safe: sync
// proves all warps finished t-1, whose P lived in s^1) -> S -> softmax ->
// sync -> P over K[s] -> PV. qt = 31-blockIdx.x so longest tiles launch first.
// ===========================================================================
#define QP 68
#define VP 72
#define SMEM_ATT ((3 * 64 * QP + 2 * 64 * VP) * 4)   // 89088 bytes

__global__ __launch_bounds__(128) void attn_mma() {
    extern __shared__ float as_[];
    float* Qs = as_;                             // [64][QP]
    float* KPb[2] = {as_ + 64 * QP, as_ + 2 * 64 * QP};
    float* Vb[2]  = {as_ + 3 * 64 * QP, as_ + 3 * 64 * QP + 64 * VP};

    const int tid  = threadIdx.x;
    const int warp = tid >> 5;
    const int lane = tid & 31;
    const int lg = lane >> 2;
    const int lt = lane & 3;
    const int wq0 = warp * 16;          // warp's first q row (local)
    const int qt = (int)(gridDim.x - 1 - blockIdx.x);   // longest first
    const int h  = blockIdx.y;
    const int b  = blockIdx.z;
    const int q0 = qt * 64;

    const float* Kbase = g_K + (size_t)(b * T_) * C_ + h * D_;
    const float* Vbase = g_V + (size_t)(b * T_) * C_ + h * D_;

    // Load Q (already tf32)
    const float* Qp = g_Q + ((size_t)(b * T_) + q0) * C_ + h * D_;
#pragma unroll
    for (int it = 0; it < 8; it++) {
        int idx = tid + it * 128;       // 0..1023
        int row = idx >> 4;
        int c   = (idx & 15) << 2;
        *(float4*)(Qs + row * QP + c) = *(const float4*)(Qp + (size_t)row * C_ + c);
    }

    // prologue: async-load tile 0 into buffer 0
    {
        const float* Kp = Kbase;
        const float* Vp = Vbase;
#pragma unroll
        for (int it = 0; it < 8; it++) {
            int idx = tid + it * 128;
            int row = idx >> 4;
            int c   = (idx & 15) << 2;
            cpa16(smem_u32(KPb[0] + row * QP + c), Kp + (size_t)row * C_ + c);
            cpa16(smem_u32(Vb[0] + row * VP + c), Vp + (size_t)row * C_ + c);
        }
        CP_COMMIT();
    }

    float m[2] = {-1e30f, -1e30f};
    float l[2] = {0.0f, 0.0f};
    float o[8][4];
#pragma unroll
    for (int nt = 0; nt < 8; nt++)
#pragma unroll
        for (int r = 0; r < 4; r++) o[nt][r] = 0.0f;

    const uint32_t* Qu = (const uint32_t*)Qs;

    for (int t = 0; t <= qt; t++) {
        const int s = t & 1;
        CP_WAIT(0);
        __syncthreads();   // tile t resident; all warps done with tile t-1 (buf s^1)

        if (t + 1 <= qt) {  // prefetch tile t+1 into buffer s^1
            const float* Kp = Kbase + (size_t)(t + 1) * 64 * C_;
            const float* Vp = Vbase + (size_t)(t + 1) * 64 * C_;
            float* kd = KPb[s ^ 1];
            float* vd = Vb[s ^ 1];
#pragma unroll
            for (int it = 0; it < 8; it++) {
                int idx = tid + it * 128;
                int row = idx >> 4;
                int c   = (idx & 15) << 2;
                cpa16(smem_u32(kd + row * QP + c), Kp + (size_t)row * C_ + c);
                cpa16(smem_u32(vd + row * VP + c), Vp + (size_t)row * C_ + c);
            }
            CP_COMMIT();
        }

        const uint32_t* KPu = (const uint32_t*)KPb[s];
        const uint32_t* Vu  = (const uint32_t*)Vb[s];

        // ---- S = Q K^T (16 q-rows x 64 keys per warp) ----
        float sc_[8][4];
#pragma unroll
        for (int nt = 0; nt < 8; nt++)
#pragma unroll
            for (int r = 0; r < 4; r++) sc_[nt][r] = 0.0f;
#pragma unroll
        for (int kt = 0; kt < 8; kt++) {
            const int k8 = kt * 8;
            uint32_t a[4];
            a[0] = Qu[(wq0 + lg)     * QP + k8 + lt];
            a[1] = Qu[(wq0 + lg + 8) * QP + k8 + lt];
            a[2] = Qu[(wq0 + lg)     * QP + k8 + 4 + lt];
            a[3] = Qu[(wq0 + lg + 8) * QP + k8 + 4 + lt];
#pragma unroll
            for (int nt = 0; nt < 8; nt++) {
                uint32_t bf[2];
                bf[0] = KPu[(nt * 8 + lg) * QP + k8 + lt];
                bf[1] = KPu[(nt * 8 + lg) * QP + k8 + 4 + lt];
                mma8(sc_[nt], a, bf);
            }
        }
#pragma unroll
        for (int nt = 0; nt < 8; nt++)
#pragma unroll
            for (int r = 0; r < 4; r++) sc_[nt][r] *= SCALE_;

        if (t == qt) {  // diagonal tile: mask key > query
            const int r0 = wq0 + lg, r1 = wq0 + lg + 8;
#pragma unroll
            for (int nt = 0; nt < 8; nt++) {
                int c0 = nt * 8 + 2 * lt, c1 = c0 + 1;
                if (c0 > r0) sc_[nt][0] = -1e30f;
                if (c1 > r0) sc_[nt][1] = -1e30f;
                if (c0 > r1) sc_[nt][2] = -1e30f;
                if (c1 > r1) sc_[nt][3] = -1e30f;
            }
        }

        // ---- online softmax (rows lg and lg+8) ----
        float mx0 = -1e30f, mx1 = -1e30f;
#pragma unroll
        for (int nt = 0; nt < 8; nt++) {
            mx0 = fmaxf(mx0, fmaxf(sc_[nt][0], sc_[nt][1]));
            mx1 = fmaxf(mx1, fmaxf(sc_[nt][2], sc_[nt][3]));
        }
        mx0 = fmaxf(mx0, __shfl_xor_sync(0xffffffffu, mx0, 1));
        mx0 = fmaxf(mx0, __shfl_xor_sync(0xffffffffu, mx0, 2));
        mx1 = fmaxf(mx1, __shfl_xor_sync(0xffffffffu, mx1, 1));
        mx1 = fmaxf(mx1, __shfl_xor_sync(0xffffffffu, mx1, 2));
        const float mn0 = fmaxf(m[0], mx0);
        const float mn1 = fmaxf(m[1], mx1);
        const float e0 = __expf(m[0] - mn0);
        const float e1 = __expf(m[1] - mn1);
        float ls0 = 0.0f, ls1 = 0.0f;
#pragma unroll
        for (int nt = 0; nt < 8; nt++) {
            sc_[nt][0] = __expf(sc_[nt][0] - mn0);
            sc_[nt][1] = __expf(sc_[nt][1] - mn0);
            sc_[nt][2] = __expf(sc_[nt][2] - mn1);
            sc_[nt][3] = __expf(sc_[nt][3] - mn1);
            ls0 += sc_[nt][0] + sc_[nt][1];
            ls1 += sc_[nt][2] + sc_[nt][3];
        }
        ls0 += __shfl_xor_sync(0xffffffffu, ls0, 1);
        ls0 += __shfl_xor_sync(0xffffffffu, ls0, 2);
        ls1 += __shfl_xor_sync(0xffffffffu, ls1, 1);
        ls1 += __shfl_xor_sync(0xffffffffu, ls1, 2);
        l[0] = l[0] * e0 + ls0;  m[0] = mn0;
        l[1] = l[1] * e1 + ls1;  m[1] = mn1;
#pragma unroll
        for (int nt = 0; nt < 8; nt++) {
            o[nt][0] *= e0; o[nt][1] *= e0;
            o[nt][2] *= e1; o[nt][3] *= e1;
        }

        __syncthreads();  // all warps finished reading K[s] before P overwrites

        // ---- write P (tf32-rounded) over K[s], warp-private rows ----
        float* KPw = KPb[s];
#pragma unroll
        for (int nt = 0; nt < 8; nt++) {
            int c0 = nt * 8 + 2 * lt;
            float* p0 = KPw + (wq0 + lg) * QP + c0;
            p0[0] = tf32r(sc_[nt][0]); p0[1] = tf32r(sc_[nt][1]);
            float* p1 = KPw + (wq0 + lg + 8) * QP + c0;
            p1[0] = tf32r(sc_[nt][2]); p1[1] = tf32r(sc_[nt][3]);
        }
        __syncwarp();

        // ---- O += P V ----
#pragma unroll
        for (int kt = 0; kt < 8; kt++) {
            const int k8 = kt * 8;
            uint32_t a[4];
            a[0] = KPu[(wq0 + lg)     * QP + k8 + lt];
            a[1] = KPu[(wq0 + lg + 8) * QP + k8 + lt];
            a[2] = KPu[(wq0 + lg)     * QP + k8 + 4 + lt];
            a[3] = KPu[(wq0 + lg + 8) * QP + k8 + 4 + lt];
#pragma unroll
            for (int nt = 0; nt < 8; nt++) {
                uint32_t bf[2];
                bf[0] = Vu[(k8 + lt)     * VP + nt * 8 + lg];
                bf[1] = Vu[(k8 + 4 + lt) * VP + nt * 8 + lg];
                mma8(o[nt], a, bf);
            }
        }
        // next iteration's CP_WAIT + __syncthreads orders buffer reuse
    }

    // ---- epilogue: O /= l, rounded tf32 (feeds Wo GEMM) ----
    const float inv0 = 1.0f / l[0];
    const float inv1 = 1.0f / l[1];
    float* Op0 = g_A + ((size_t)(b * T_) + q0 + wq0 + lg) * C_ + h * D_;
    float* Op1 = g_A + ((size_t)(b * T_) + q0 + wq0 + lg + 8) * C_ + h * D_;
#pragma unroll
    for (int nt = 0; nt < 8; nt++) {
        int c0 = nt * 8 + 2 * lt;
        *(float2*)(Op0 + c0) =
            make_float2(tf32r(o[nt][0] * inv0), tf32r(o[nt][1] * inv0));
        *(float2*)(Op1 + c0) =
            make_float2(tf32r(o[nt][2] * inv1), tf32r(o[nt][3] * inv1));
    }
}

extern "C" void kernel_launch(void* const* d_in, const int* in_sizes, int n_in,
                              void* d_out, int out_size) {
    const float* x  = (const float*)d_in[0];
    const float* Wq = (const float*)d_in[1];
    const float* Wk = (const float*)d_in[2];
    const float* Wv = (const float*)d_in[3];
    const float* Wo = (const float*)d_in[4];

    float* xr;
    cudaGetSymbolAddress((void**)&xr, g_X);

    cudaFuncSetAttribute(gemm_mma_qkv, cudaFuncAttributeMaxDynamicSharedMemorySize, SMEM_MMA);
    cudaFuncSetAttribute(gemm_mma_wo,  cudaFuncAttributeMaxDynamicSharedMemorySize, SMEM_MMA);
    cudaFuncSetAttribute(attn_mma,     cudaFuncAttributeMaxDynamicSharedMemorySize, SMEM_ATT);

    // tf32 rounding pre-pass: x, then all four weights in one launch
    cvt_tf32_kernel<<<(M_ * C_) / 1024, 256>>>(x, xr);
    cvt_tf32_w4<<<dim3((C_ * C_) / 1024, 1, 4), 256>>>(Wq, Wk, Wv, Wo);

    dim3 gqkv(C_ / 128, M_ / 128, 3);   // (8, 32, 3)
    gemm_mma_qkv<<<gqkv, 256, SMEM_MMA>>>();
    attn_mma<<<dim3(T_ / 64, H_, B_), 128, SMEM_ATT>>>();
    gemm_mma_wo<<<dim3(C_ / 128, M_ / 128), 256, SMEM_MMA>>>((float*)d_out);
}

// round 16
// speedup vs baseline: 1.0219x; 1.0219x over previous
#include <cuda_runtime.h>
#include <cstdint>
#include <math.h>

#define B_ 2
#define T_ 2048
#define C_ 1024
#define H_ 16
#define D_ 64
#define M_ (B_ * T_)          // 4096 rows
#define SCALE_ 0.125f          // 1/sqrt(64)

// Scratch (allocation-free rule: device globals)
static __device__ float g_Q[(size_t)M_ * C_];
static __device__ float g_K[(size_t)M_ * C_];
static __device__ float g_V[(size_t)M_ * C_];
static __device__ float g_A[(size_t)M_ * C_];
// tf32-rounded operand copies
static __device__ float g_X[(size_t)M_ * C_];
static __device__ float g_Wq[(size_t)C_ * C_];
static __device__ float g_Wk[(size_t)C_ * C_];
static __device__ float g_Wv[(size_t)C_ * C_];
static __device__ float g_Wo[(size_t)C_ * C_];

// ===========================================================================
// helpers
// ===========================================================================
__device__ __forceinline__ uint32_t smem_u32(const void* p) {
    uint32_t a;
    asm("{ .reg .u64 t; cvta.to.shared.u64 t, %1; cvt.u32.u64 %0, t; }"
        : "=r"(a) : "l"(p));
    return a;
}
__device__ __forceinline__ float tf32r(float x) {
    uint32_t u;
    asm("cvt.rna.tf32.f32 %0, %1;" : "=r"(u) : "f"(x));
    return __uint_as_float(u);
}
__device__ __forceinline__ void cpa16(uint32_t dst, const float* src) {
    asm volatile("cp.async.ca.shared.global [%0], [%1], 16;" :: "r"(dst), "l"(src));
}
#define CP_COMMIT() asm volatile("cp.async.commit_group;" ::: "memory")
#define CP_WAIT(n)  asm volatile("cp.async.wait_group %0;" :: "n"(n) : "memory")

__device__ __forceinline__ void mma8(float* c, const uint32_t* a, const uint32_t* b) {
    asm volatile(
        "mma.sync.aligned.m16n8k8.row.col.f32.tf32.tf32.f32 "
        "{%0,%1,%2,%3}, {%4,%5,%6,%7}, {%8,%9}, {%0,%1,%2,%3};"
        : "+f"(c[0]), "+f"(c[1]), "+f"(c[2]), "+f"(c[3])
        : "r"(a[0]), "r"(a[1]), "r"(a[2]), "r"(a[3]), "r"(b[0]), "r"(b[1]));
}

// ===========================================================================
// Pre-pass: tf32 rounding (exact tf32 operands for cp.async path)
// ===========================================================================
__global__ __launch_bounds__(256) void cvt_tf32_kernel(const float* __restrict__ in,
                                                       float* __restrict__ out) {
    size_t i = ((size_t)blockIdx.x * 256 + threadIdx.x) * 4;
    float4 v = *(const float4*)(in + i);
    v.x = tf32r(v.x); v.y = tf32r(v.y); v.z = tf32r(v.z); v.w = tf32r(v.w);
    *(float4*)(out + i) = v;
}

// All four weight matrices in one launch (gridDim.z selects the pair).
__global__ __launch_bounds__(256) void cvt_tf32_w4(const float* __restrict__ w0,
                                                   const float* __restrict__ w1,
                                                   const float* __restrict__ w2,
                                                   const float* __restrict__ w3) {
    const float* in = (blockIdx.z == 0) ? w0 : (blockIdx.z == 1) ? w1
                    : (blockIdx.z == 2) ? w2 : w3;
    float* out = (blockIdx.z == 0) ? g_Wq : (blockIdx.z == 1) ? g_Wk
               : (blockIdx.z == 2) ? g_Wv : g_Wo;
    size_t i = ((size_t)blockIdx.x * 256 + threadIdx.x) * 4;
    float4 v = *(const float4*)(in + i);
    v.x = tf32r(v.x); v.y = tf32r(v.y); v.z = tf32r(v.z); v.w = tf32r(v.w);
    *(float4*)(out + i) = v;
}

// ===========================================================================
// tf32 mma.sync GEMM:  C[M,N] = A[M,K] @ W[N,K]^T, A/W pre-rounded to tf32.
// CTA 128x128, 8 warps (warp tile 64x32), k-chunk 16, 3-stage cp.async.
// smem rows padded to 20 floats -> conflict-free fragment loads.
// ROUND: tf32-round outputs (Q/K/V feed attention's raw loads).
// ===========================================================================
#define KC 16
#define STAGES 3
#define TSTR 20                       // floats per smem row
#define TILE_F (128 * TSTR)           // floats per tile per stage
#define SMEM_MMA (STAGES * 2 * TILE_F * 4)   // 61440 bytes
#define NCHUNK (C_ / KC)              // 64

__device__ __forceinline__ void load_chunk(const float* __restrict__ Ab,
                                           const float* __restrict__ Wb,
                                           float* sA, float* sB,
                                           int c, int tid) {
    const int k0 = c * KC;
#pragma unroll
    for (int it = 0; it < 2; it++) {
        int idx = tid + it * 256;        // 0..511
        int row = idx >> 2;              // 0..127
        int f4  = (idx & 3) << 2;        // 0,4,8,12
        cpa16(smem_u32(sA + row * TSTR + f4), Ab + (size_t)row * C_ + k0 + f4);
        cpa16(smem_u32(sB + row * TSTR + f4), Wb + (size_t)row * C_ + k0 + f4);
    }
}

template <bool ROUND>
__device__ __forceinline__ void gemm_mma_body(const float* __restrict__ A,
                                              const float* __restrict__ W,
                                              float* __restrict__ Cout,
                                              int bm, int bn) {
    extern __shared__ float smem[];
    float* sA = smem;                       // [STAGES][TILE_F]
    float* sB = smem + STAGES * TILE_F;     // [STAGES][TILE_F]

    const int tid = threadIdx.x;
    const int warp = tid >> 5;
    const int lane = tid & 31;
    const int wm = (warp & 1) * 64;
    const int wn = (warp >> 1) * 32;
    const int lg = lane >> 2;      // group id 0..7
    const int lt = lane & 3;       // thread-in-group

    const float* Ab = A + (size_t)bm * C_;
    const float* Wb = W + (size_t)bn * C_;

    float acc[4][4][4];
#pragma unroll
    for (int i = 0; i < 4; i++)
#pragma unroll
        for (int j = 0; j < 4; j++)
#pragma unroll
            for (int r = 0; r < 4; r++) acc[i][j][r] = 0.0f;

    // prologue: stages 0..STAGES-2
#pragma unroll
    for (int c = 0; c < STAGES - 1; c++) {
        load_chunk(Ab, Wb, sA + c * TILE_F, sB + c * TILE_F, c, tid);
        CP_COMMIT();
    }

    for (int c = 0; c < NCHUNK; c++) {
        CP_WAIT(STAGES - 2);
        __syncthreads();
        const int nc = c + STAGES - 1;
        if (nc < NCHUNK)
            load_chunk(Ab, Wb, sA + (nc % STAGES) * TILE_F,
                       sB + (nc % STAGES) * TILE_F, nc, tid);
        CP_COMMIT();

        const uint32_t* cA = (const uint32_t*)(sA + (c % STAGES) * TILE_F);
        const uint32_t* cB = (const uint32_t*)(sB + (c % STAGES) * TILE_F);
#pragma unroll
        for (int kk = 0; kk < 2; kk++) {
            const int k8 = kk * 8;
            uint32_t af[4][4];
#pragma unroll
            for (int mt = 0; mt < 4; mt++) {
                int r0 = wm + mt * 16 + lg;
                af[mt][0] = cA[(r0)     * TSTR + k8 + lt];
                af[mt][1] = cA[(r0 + 8) * TSTR + k8 + lt];
                af[mt][2] = cA[(r0)     * TSTR + k8 + 4 + lt];
                af[mt][3] = cA[(r0 + 8) * TSTR + k8 + 4 + lt];
            }
            uint32_t bf[4][2];
#pragma unroll
            for (int nt = 0; nt < 4; nt++) {
                int n0 = wn + nt * 8 + lg;
                bf[nt][0] = cB[n0 * TSTR + k8 + lt];
                bf[nt][1] = cB[n0 * TSTR + k8 + 4 + lt];
            }
#pragma unroll
            for (int mt = 0; mt < 4; mt++)
#pragma unroll
                for (int nt = 0; nt < 4; nt++)
                    mma8(acc[mt][nt], af[mt], bf[nt]);
        }
    }

    // epilogue: c0,c1 -> (row, 2lt), (row, 2lt+1); c2,c3 -> row+8
#pragma unroll
    for (int mt = 0; mt < 4; mt++) {
#pragma unroll
        for (int nt = 0; nt < 4; nt++) {
            int row = bm + wm + mt * 16 + lg;
            int col = bn + wn + nt * 8 + lt * 2;
            float v0 = acc[mt][nt][0], v1 = acc[mt][nt][1];
            float v2 = acc[mt][nt][2], v3 = acc[mt][nt][3];
            if (ROUND) { v0 = tf32r(v0); v1 = tf32r(v1); v2 = tf32r(v2); v3 = tf32r(v3); }
            *(float2*)(Cout + (size_t)row * C_ + col) = make_float2(v0, v1);
            *(float2*)(Cout + (size_t)(row + 8) * C_ + col) = make_float2(v2, v3);
        }
    }
}

__global__ __launch_bounds__(256) void gemm_mma_qkv() {
    const float* W = (blockIdx.z == 0) ? g_Wq : (blockIdx.z == 1) ? g_Wk : g_Wv;
    float* Cout = (blockIdx.z == 0) ? g_Q : (blockIdx.z == 1) ? g_K : g_V;
    gemm_mma_body<true>(g_X, W, Cout, blockIdx.y * 128, blockIdx.x * 128);
}
__global__ __launch_bounds__(256) void gemm_mma_wo(float* __restrict__ Cout) {
    gemm_mma_body<false>(g_A, g_Wo, Cout, blockIdx.y * 128, blockIdx.x * 128);
}

// ===========================================================================
// Flash-attention, mma.sync tf32, 128-QUERY blocks (8 warps, 256 threads).
// Q/K/V pre-rounded to tf32 by the QKV GEMM epilogue -> raw loads here.
// Smem: Q[128][68], KP[128][68] (K tile rows 0..63; P rows 0..127), V[64][72]
// = 88,064 B -> 2 CTAs/SM x 8 warps = 16 warps/SM (same as best config) with
// HALF the K/V traffic and barriers per unit work. Warps fully below a
// diagonal tile's keys skip compute (warp-uniform; barriers preserved).
// qt reversed so longest blocks launch first.
// ===========================================================================
#define QP 68
#define VP 72
#define SMEM_ATT ((2 * 128 * QP + 64 * VP) * 4)   // 88064 bytes

__global__ __launch_bounds__(256) void attn_mma() {
    extern __shared__ float as_[];
    float* Qs  = as_;                     // [128][QP]
    float* KPs = as_ + 128 * QP;          // [128][QP]: K rows 0..63, P rows 0..127
    float* Vs  = as_ + 2 * 128 * QP;      // [64][VP]
    const uint32_t* Qu  = (const uint32_t*)Qs;
    const uint32_t* KPu = (const uint32_t*)KPs;
    const uint32_t* Vu  = (const uint32_t*)Vs;

    const int tid  = threadIdx.x;
    const int warp = tid >> 5;            // 0..7
    const int lane = tid & 31;
    const int lg = lane >> 2;
    const int lt = lane & 3;
    const int wq0 = warp * 16;            // warp's first local q row
    const int qt = (int)(gridDim.x - 1 - blockIdx.x);   // longest first
    const int h  = blockIdx.y;
    const int b  = blockIdx.z;
    const int q0 = qt * 128;
    const int ntiles = 2 * qt + 2;

    const float* Kbase = g_K + (size_t)(b * T_) * C_ + h * D_;
    const float* Vbase = g_V + (size_t)(b * T_) * C_ + h * D_;

    // Load Q (already tf32): 128 rows x 64 cols
    const float* Qp = g_Q + ((size_t)(b * T_) + q0) * C_ + h * D_;
#pragma unroll
    for (int it = 0; it < 8; it++) {
        int idx = tid + it * 256;         // 0..2047
        int row = idx >> 4;               // 0..127
        int c   = (idx & 15) << 2;
        *(float4*)(Qs + row * QP + c) = *(const float4*)(Qp + (size_t)row * C_ + c);
    }

    float m[2] = {-1e30f, -1e30f};
    float l[2] = {0.0f, 0.0f};
    float o[8][4];
#pragma unroll
    for (int nt = 0; nt < 8; nt++)
#pragma unroll
        for (int r = 0; r < 4; r++) o[nt][r] = 0.0f;

    for (int t = 0; t < ntiles; t++) {
        // ---- load K,V tile (64 rows x 64 cols each) ----
        const float* Kp = Kbase + (size_t)t * 64 * C_;
        const float* Vp = Vbase + (size_t)t * 64 * C_;
#pragma unroll
        for (int it = 0; it < 4; it++) {
            int idx = tid + it * 256;     // 0..1023
            int row = idx >> 4;           // 0..63
            int c   = (idx & 15) << 2;
            *(float4*)(KPs + row * QP + c) = *(const float4*)(Kp + (size_t)row * C_ + c);
            *(float4*)(Vs + row * VP + c) = *(const float4*)(Vp + (size_t)row * C_ + c);
        }
        __syncthreads();

        // warp active iff some key in tile <= some query of this warp
        const bool active = (64 * t) <= (q0 + wq0 + 15);
        float sc_[8][4];

        if (active) {
            // ---- S = Q K^T (16 q-rows x 64 keys per warp) ----
#pragma unroll
            for (int nt = 0; nt < 8; nt++)
#pragma unroll
                for (int r = 0; r < 4; r++) sc_[nt][r] = 0.0f;
#pragma unroll
            for (int kt = 0; kt < 8; kt++) {
                const int k8 = kt * 8;
                uint32_t a[4];
                a[0] = Qu[(wq0 + lg)     * QP + k8 + lt];
                a[1] = Qu[(wq0 + lg + 8) * QP + k8 + lt];
                a[2] = Qu[(wq0 + lg)     * QP + k8 + 4 + lt];
                a[3] = Qu[(wq0 + lg + 8) * QP + k8 + 4 + lt];
#pragma unroll
                for (int nt = 0; nt < 8; nt++) {
                    uint32_t bf[2];
                    bf[0] = KPu[(nt * 8 + lg) * QP + k8 + lt];
                    bf[1] = KPu[(nt * 8 + lg) * QP + k8 + 4 + lt];
                    mma8(sc_[nt], a, bf);
                }
            }
#pragma unroll
            for (int nt = 0; nt < 8; nt++)
#pragma unroll
                for (int r = 0; r < 4; r++) sc_[nt][r] *= SCALE_;

            if (64 * t + 63 > q0 + wq0) {  // tile may violate causality for this warp
                const int r0 = q0 + wq0 + lg, r1 = r0 + 8;
                const int kbase = 64 * t;
#pragma unroll
                for (int nt = 0; nt < 8; nt++) {
                    int c0 = kbase + nt * 8 + 2 * lt, c1 = c0 + 1;
                    if (c0 > r0) sc_[nt][0] = -1e30f;
                    if (c1 > r0) sc_[nt][1] = -1e30f;
                    if (c0 > r1) sc_[nt][2] = -1e30f;
                    if (c1 > r1) sc_[nt][3] = -1e30f;
                }
            }

            // ---- online softmax (rows lg and lg+8) ----
            float mx0 = -1e30f, mx1 = -1e30f;
#pragma unroll
            for (int nt = 0; nt < 8; nt++) {
                mx0 = fmaxf(mx0, fmaxf(sc_[nt][0], sc_[nt][1]));
                mx1 = fmaxf(mx1, fmaxf(sc_[nt][2], sc_[nt][3]));
            }
            mx0 = fmaxf(mx0, __shfl_xor_sync(0xffffffffu, mx0, 1));
            mx0 = fmaxf(mx0, __shfl_xor_sync(0xffffffffu, mx0, 2));
            mx1 = fmaxf(mx1, __shfl_xor_sync(0xffffffffu, mx1, 1));
            mx1 = fmaxf(mx1, __shfl_xor_sync(0xffffffffu, mx1, 2));
            const float mn0 = fmaxf(m[0], mx0);
            const float mn1 = fmaxf(m[1], mx1);
            const float e0 = __expf(m[0] - mn0);
            const float e1 = __expf(m[1] - mn1);
            float ls0 = 0.0f, ls1 = 0.0f;
#pragma unroll
            for (int nt = 0; nt < 8; nt++) {
                sc_[nt][0] = __expf(sc_[nt][0] - mn0);
                sc_[nt][1] = __expf(sc_[nt][1] - mn0);
                sc_[nt][2] = __expf(sc_[nt][2] - mn1);
                sc_[nt][3] = __expf(sc_[nt][3] - mn1);
                ls0 += sc_[nt][0] + sc_[nt][1];
                ls1 += sc_[nt][2] + sc_[nt][3];
            }
            ls0 += __shfl_xor_sync(0xffffffffu, ls0, 1);
            ls0 += __shfl_xor_sync(0xffffffffu, ls0, 2);
            ls1 += __shfl_xor_sync(0xffffffffu, ls1, 1);
            ls1 += __shfl_xor_sync(0xffffffffu, ls1, 2);
            l[0] = l[0] * e0 + ls0;  m[0] = mn0;
            l[1] = l[1] * e1 + ls1;  m[1] = mn1;
#pragma unroll
            for (int nt = 0; nt < 8; nt++) {
                o[nt][0] *= e0; o[nt][1] *= e0;
                o[nt][2] *= e1; o[nt][3] *= e1;
            }
        }

        __syncthreads();  // all warps done reading K rows before P overwrites

        if (active) {
            // ---- write P (tf32-rounded), warp-private rows ----
#pragma unroll
            for (int nt = 0; nt < 8; nt++) {
                int c0 = nt * 8 + 2 * lt;
                float* p0 = KPs + (wq0 + lg) * QP + c0;
                p0[0] = tf32r(sc_[nt][0]); p0[1] = tf32r(sc_[nt][1]);
                float* p1 = KPs + (wq0 + lg + 8) * QP + c0;
                p1[0] = tf32r(sc_[nt][2]); p1[1] = tf32r(sc_[nt][3]);
            }
            __syncwarp();

            // ---- O += P V ----
#pragma unroll
            for (int kt = 0; kt < 8; kt++) {
                const int k8 = kt * 8;
                uint32_t a[4];
                a[0] = KPu[(wq0 + lg)     * QP + k8 + lt];
                a[1] = KPu[(wq0 + lg + 8) * QP + k8 + lt];
                a[2] = KPu[(wq0 + lg)     * QP + k8 + 4 + lt];
                a[3] = KPu[(wq0 + lg + 8) * QP + k8 + 4 + lt];
#pragma unroll
                for (int nt = 0; nt < 8; nt++) {
                    uint32_t bf[2];
                    bf[0] = Vu[(k8 + lt)     * VP + nt * 8 + lg];
                    bf[1] = Vu[(k8 + 4 + lt) * VP + nt * 8 + lg];
                    mma8(o[nt], a, bf);
                }
            }
        }
        __syncthreads();  // before next tile load overwrites K/V
    }

    // ---- epilogue: O /= l, rounded tf32 (feeds Wo GEMM) ----
    const float inv0 = 1.0f / l[0];
    const float inv1 = 1.0f / l[1];
    float* Op0 = g_A + ((size_t)(b * T_) + q0 + wq0 + lg) * C_ + h * D_;
    float* Op1 = g_A + ((size_t)(b * T_) + q0 + wq0 + lg + 8) * C_ + h * D_;
#pragma unroll
    for (int nt = 0; nt < 8; nt++) {
        int c0 = nt * 8 + 2 * lt;
        *(float2*)(Op0 + c0) =
            make_float2(tf32r(o[nt][0] * inv0), tf32r(o[nt][1] * inv0));
        *(float2*)(Op1 + c0) =
            make_float2(tf32r(o[nt][2] * inv1), tf32r(o[nt][3] * inv1));
    }
}

extern "C" void kernel_launch(void* const* d_in, const int* in_sizes, int n_in,
                              void* d_out, int out_size) {
    const float* x  = (const float*)d_in[0];
    const float* Wq = (const float*)d_in[1];
    const float* Wk = (const float*)d_in[2];
    const float* Wv = (const float*)d_in[3];
    const float* Wo = (const float*)d_in[4];

    float* xr;
    cudaGetSymbolAddress((void**)&xr, g_X);

    cudaFuncSetAttribute(gemm_mma_qkv, cudaFuncAttributeMaxDynamicSharedMemorySize, SMEM_MMA);
    cudaFuncSetAttribute(gemm_mma_wo,  cudaFuncAttributeMaxDynamicSharedMemorySize, SMEM_MMA);
    cudaFuncSetAttribute(attn_mma,     cudaFuncAttributeMaxDynamicSharedMemorySize, SMEM_ATT);

    // tf32 rounding pre-pass: x, then all four weights in one launch
    cvt_tf32_kernel<<<(M_ * C_) / 1024, 256>>>(x, xr);
    cvt_tf32_w4<<<dim3((C_ * C_) / 1024, 1, 4), 256>>>(Wq, Wk, Wv, Wo);

    dim3 gqkv(C_ / 128, M_ / 128, 3);   // (8, 32, 3)
    gemm_mma_qkv<<<gqkv, 256, SMEM_MMA>>>();
    attn_mma<<<dim3(T_ / 128, H_, B_), 256, SMEM_ATT>>>();
    gemm_mma_wo<<<dim3(C_ / 128, M_ / 128), 256, SMEM_MMA>>>((float*)d_out);
}